// round 2
// baseline (speedup 1.0000x reference)
#include <cuda_runtime.h>

#define N_ROWS 16384
#define M_COLS 2048
#define D_DIM  128
#define K_CONST 0.1f
#define GAMMA_CONST 1.0f

// ---------------- scratch (static device globals; no allocation) -------------
__device__ float  g_sum_x[128];     // sum over rows of x  [D]
__device__ float  g_sum_nx2;        // sum_i ||x_i||^2
__device__ float  g_nx2[N_ROWS];    // per-row ||x_i||^2
__device__ float4 g_pstat[M_COLS];  // {np2, 1/(np_norm*sqrt(ssd)), psi, 1+np2}
__device__ double g_acc;            // global loss accumulator

// ---------------- init: zero accumulators every replay -----------------------
__global__ void init_kernel() {
    int t = threadIdx.x;
    if (t < 128) g_sum_x[t] = 0.f;
    if (t == 0) { g_sum_nx2 = 0.f; g_acc = 0.0; }
}

// ---------------- x stats: nx2[i], sum_x[d], sum_nx2 -------------------------
__global__ void xstats_kernel(const float* __restrict__ x) {
    int lane = threadIdx.x & 31;
    int wid  = threadIdx.x >> 5;
    int gw   = blockIdx.x * 8 + wid;       // 256 blocks * 8 warps = 2048 warps
    int base = gw * 8;                      // 8 rows per warp

    float sx0 = 0.f, sx1 = 0.f, sx2 = 0.f, sx3 = 0.f;
    float snx2_part = 0.f;                  // per-lane partial of sum ||x||^2

    #pragma unroll
    for (int rr = 0; rr < 8; ++rr) {
        int row = base + rr;
        float4 v = ((const float4*)(x + (size_t)row * D_DIM))[lane];
        float d = v.x*v.x + v.y*v.y + v.z*v.z + v.w*v.w;
        snx2_part += d;
        float dr = d;
        #pragma unroll
        for (int o = 16; o; o >>= 1) dr += __shfl_xor_sync(0xffffffffu, dr, o);
        if (lane == 0) g_nx2[row] = dr;
        sx0 += v.x; sx1 += v.y; sx2 += v.z; sx3 += v.w;
    }
    // per-lane owns dims 4*lane .. 4*lane+3
    atomicAdd(&g_sum_x[lane * 4 + 0], sx0);
    atomicAdd(&g_sum_x[lane * 4 + 1], sx1);
    atomicAdd(&g_sum_x[lane * 4 + 2], sx2);
    atomicAdd(&g_sum_x[lane * 4 + 3], sx3);
    #pragma unroll
    for (int o = 16; o; o >>= 1) snx2_part += __shfl_xor_sync(0xffffffffu, snx2_part, o);
    if (lane == 0) atomicAdd(&g_sum_nx2, snx2_part);
}

// ---------------- p stats: per-column constants ------------------------------
__global__ void pstats_kernel(const float* __restrict__ p) {
    int j = blockIdx.x * blockDim.x + threadIdx.x;
    if (j >= M_COLS) return;
    const float4* pr = (const float4*)(p + (size_t)j * D_DIM);
    float np2 = 0.f, sxdot = 0.f;
    #pragma unroll
    for (int q = 0; q < 32; ++q) {
        float4 v = pr[q];
        float4 s = ((const float4*)g_sum_x)[q];
        np2   += v.x*v.x + v.y*v.y + v.z*v.z + v.w*v.w;
        sxdot += v.x*s.x + v.y*s.y + v.z*s.z + v.w*s.w;
    }
    float ssd    = g_sum_nx2 + (float)N_ROWS * np2 - 2.f * sxdot; // sum_i ||x_i-p_j||^2
    float inv_np = rsqrtf(np2);
    float invc   = rsqrtf(np2 * ssd);     // 1/(||p|| * sqrt(ssd))
    float psi    = asinf(K_CONST * (1.f - np2) * inv_np);
    g_pstat[j]   = make_float4(np2, invc, psi, 1.f + np2);
}

// ---------------- fused GEMM + epilogue --------------------------------------
// 128x128 tile, 256 threads, 8x8 microtiles, K staged in 4 chunks of 32.
__global__ void __launch_bounds__(256, 2)
main_kernel(const float* __restrict__ x, const float* __restrict__ p,
            const int* __restrict__ labels) {
    __shared__ float As[32][132];   // k-major: As[k][i], pitch 132 (bank skew)
    __shared__ float Bs[32][132];   // k-major: Bs[k][j]
    __shared__ float wsum[8];

    int tid = threadIdx.x;
    int tx  = tid & 15;             // column group (0..15)
    int ty  = tid >> 4;             // row group (0..15)
    int rowBase = blockIdx.y * 128;
    int colBase = blockIdx.x * 128;

    float acc[8][8];
    #pragma unroll
    for (int r = 0; r < 8; ++r)
        #pragma unroll
        for (int c = 0; c < 8; ++c) acc[r][c] = 0.f;

    int li  = tid >> 3;             // 0..31 : row within quarter
    int lk4 = tid & 7;              // 0..7  : float4 index in k-chunk

    for (int kc = 0; kc < D_DIM; kc += 32) {
        #pragma unroll
        for (int q = 0; q < 4; ++q) {
            int r = li + q * 32;    // 0..127
            float4 av = *(const float4*)(x + (size_t)(rowBase + r) * D_DIM + kc + lk4 * 4);
            float4 bv = *(const float4*)(p + (size_t)(colBase + r) * D_DIM + kc + lk4 * 4);
            int k = lk4 * 4;
            As[k+0][r] = av.x; As[k+1][r] = av.y; As[k+2][r] = av.z; As[k+3][r] = av.w;
            Bs[k+0][r] = bv.x; Bs[k+1][r] = bv.y; Bs[k+2][r] = bv.z; Bs[k+3][r] = bv.w;
        }
        __syncthreads();
        #pragma unroll
        for (int k = 0; k < 32; ++k) {
            float4 a0 = *(const float4*)&As[k][ty * 8];
            float4 a1 = *(const float4*)&As[k][ty * 8 + 4];
            float4 b0 = *(const float4*)&Bs[k][tx * 8];
            float4 b1 = *(const float4*)&Bs[k][tx * 8 + 4];
            float a[8] = {a0.x, a0.y, a0.z, a0.w, a1.x, a1.y, a1.z, a1.w};
            float b[8] = {b0.x, b0.y, b0.z, b0.w, b1.x, b1.y, b1.z, b1.w};
            #pragma unroll
            for (int r = 0; r < 8; ++r)
                #pragma unroll
                for (int c = 0; c < 8; ++c)
                    acc[r][c] = fmaf(a[r], b[c], acc[r][c]);
        }
        __syncthreads();
    }

    // per-column / per-row constants
    float np2v[8], invcv[8], psiv[8], a1v[8];
    #pragma unroll
    for (int c = 0; c < 8; ++c) {
        float4 ps = g_pstat[colBase + tx * 8 + c];
        np2v[c] = ps.x; invcv[c] = ps.y; psiv[c] = ps.z; a1v[c] = ps.w;
    }
    float bx[8]; int lab[8];
    #pragma unroll
    for (int r = 0; r < 8; ++r) {
        bx[r]  = g_nx2[rowBase + ty * 8 + r];
        lab[r] = labels[rowBase + ty * 8 + r];
    }

    float local = 0.f;
    #pragma unroll
    for (int r = 0; r < 8; ++r) {
        float b1 = 1.f + bx[r];
        #pragma unroll
        for (int c = 0; c < 8; ++c) {
            float dot   = acc[r][c];
            float num   = dot * a1v[c] - np2v[c] * b1;
            float t     = fmaf(np2v[c], bx[r], 1.f) - 2.f * dot;
            float ratio = num * invcv[c] * rsqrtf(t);
            ratio       = fminf(1.f, fmaxf(-1.f, ratio));
            float angle = acosf(ratio);
            float ang   = fmaxf(0.f, angle - psiv[c]);
            float hinge = fmaxf(0.f, GAMMA_CONST - ang);
            local += hinge;
            if (colBase + tx * 8 + c == lab[r]) local += ang - hinge;
        }
    }

    // block reduce -> one double atomic per block
    #pragma unroll
    for (int o = 16; o; o >>= 1) local += __shfl_xor_sync(0xffffffffu, local, o);
    if ((tid & 31) == 0) wsum[tid >> 5] = local;
    __syncthreads();
    if (tid == 0) {
        float s = 0.f;
        #pragma unroll
        for (int w = 0; w < 8; ++w) s += wsum[w];
        atomicAdd(&g_acc, (double)s);
    }
}

// ---------------- finalize ----------------------------------------------------
__global__ void finish_kernel(float* __restrict__ out) {
    out[0] = (float)(g_acc / (double)N_ROWS);
}

// ---------------- launch ------------------------------------------------------
extern "C" void kernel_launch(void* const* d_in, const int* in_sizes, int n_in,
                              void* d_out, int out_size) {
    const float* x      = (const float*)d_in[0];
    const float* p      = (const float*)d_in[1];
    const int*   labels = (const int*)d_in[2];
    float* out = (float*)d_out;

    init_kernel<<<1, 128>>>();
    xstats_kernel<<<256, 256>>>(x);
    pstats_kernel<<<8, 256>>>(p);
    dim3 grid(M_COLS / 128, N_ROWS / 128);   // (16, 128)
    main_kernel<<<grid, 256>>>(x, p, labels);
    finish_kernel<<<1, 1>>>(out);
}

// round 5
// speedup vs baseline: 2.5083x; 2.5083x over previous
#include <cuda_runtime.h>
#include <cuda_bf16.h>
#include <cstdint>

#define N_ROWS 16384
#define M_COLS 2048
#define D_DIM  128
#define K_CONST 0.1f
#define GAMMA_CONST 1.0f

// ======================= PTX helpers ========================================
__device__ __forceinline__ uint32_t smem_u32(const void* p) {
    uint32_t a;
    asm("{ .reg .u64 t; cvta.to.shared.u64 t, %1; cvt.u32.u64 %0, t; }" : "=r"(a) : "l"(p));
    return a;
}
#define CPA16(dst, src) \
    asm volatile("cp.async.cg.shared.global [%0], [%1], 16;" :: "r"(dst), "l"(src))
#define CPA_COMMIT() asm volatile("cp.async.commit_group;" ::: "memory")
#define CPA_WAIT0()  asm volatile("cp.async.wait_group 0;" ::: "memory")

__device__ __forceinline__ void ldsm4(uint32_t* r, uint32_t addr) {
    asm volatile("ldmatrix.sync.aligned.m8n8.x4.shared.b16 {%0,%1,%2,%3}, [%4];"
        : "=r"(r[0]), "=r"(r[1]), "=r"(r[2]), "=r"(r[3]) : "r"(addr));
}
__device__ __forceinline__ void mma16816(float* c, const uint32_t* a, uint32_t b0, uint32_t b1) {
    asm volatile("mma.sync.aligned.m16n8k16.row.col.f32.bf16.bf16.f32 "
        "{%0,%1,%2,%3}, {%4,%5,%6,%7}, {%8,%9}, {%0,%1,%2,%3};"
        : "+f"(c[0]), "+f"(c[1]), "+f"(c[2]), "+f"(c[3])
        : "r"(a[0]), "r"(a[1]), "r"(a[2]), "r"(a[3]), "r"(b0), "r"(b1));
}

// ======================= scratch device globals ==============================
__device__ __align__(16) __nv_bfloat16 g_xhi[N_ROWS * D_DIM];
__device__ __align__(16) __nv_bfloat16 g_xlo[N_ROWS * D_DIM];
__device__ __align__(16) __nv_bfloat16 g_phi[M_COLS * D_DIM];
__device__ __align__(16) __nv_bfloat16 g_plo[M_COLS * D_DIM];
__device__ float  g_sum_x[D_DIM];
__device__ float  g_sum_nx2;
__device__ float  g_nx2[N_ROWS];
__device__ float4 g_pstat[M_COLS];   // {np2, 1/(||p||*sqrt(ssd)), psi, 1+np2}
__device__ double g_acc;

// ======================= prep kernels ========================================
__global__ void init_kernel() {
    int t = threadIdx.x;
    if (t < D_DIM) g_sum_x[t] = 0.f;
    if (t == 0) { g_sum_nx2 = 0.f; g_acc = 0.0; }
}

__device__ __forceinline__ void split2(float a, float b, uint32_t& hi, uint32_t& lo) {
    __nv_bfloat162 h = __floats2bfloat162_rn(a, b);
    float ra = a - __bfloat162float(__low2bfloat16(h));
    float rb = b - __bfloat162float(__high2bfloat16(h));
    __nv_bfloat162 l = __floats2bfloat162_rn(ra, rb);
    hi = *(uint32_t*)&h; lo = *(uint32_t*)&l;
}

__global__ void xstats_kernel(const float* __restrict__ x) {
    int lane = threadIdx.x & 31;
    int wid  = threadIdx.x >> 5;
    int base = (blockIdx.x * 8 + wid) * 8;

    float sx0 = 0.f, sx1 = 0.f, sx2 = 0.f, sx3 = 0.f;
    float snx2 = 0.f;
    #pragma unroll
    for (int rr = 0; rr < 8; ++rr) {
        int row = base + rr;
        float4 v = ((const float4*)(x + (size_t)row * D_DIM))[lane];
        uint2 hi, lo;
        split2(v.x, v.y, hi.x, lo.x);
        split2(v.z, v.w, hi.y, lo.y);
        *(uint2*)(g_xhi + (size_t)row * D_DIM + lane * 4) = hi;
        *(uint2*)(g_xlo + (size_t)row * D_DIM + lane * 4) = lo;
        float d = v.x*v.x + v.y*v.y + v.z*v.z + v.w*v.w;
        snx2 += d;
        float dr = d;
        #pragma unroll
        for (int o = 16; o; o >>= 1) dr += __shfl_xor_sync(0xffffffffu, dr, o);
        if (lane == 0) g_nx2[row] = dr;
        sx0 += v.x; sx1 += v.y; sx2 += v.z; sx3 += v.w;
    }
    atomicAdd(&g_sum_x[lane*4+0], sx0);
    atomicAdd(&g_sum_x[lane*4+1], sx1);
    atomicAdd(&g_sum_x[lane*4+2], sx2);
    atomicAdd(&g_sum_x[lane*4+3], sx3);
    #pragma unroll
    for (int o = 16; o; o >>= 1) snx2 += __shfl_xor_sync(0xffffffffu, snx2, o);
    if (lane == 0) atomicAdd(&g_sum_nx2, snx2);
}

__global__ void pstats_kernel(const float* __restrict__ p) {
    int j = blockIdx.x * blockDim.x + threadIdx.x;
    if (j >= M_COLS) return;
    const float4* pr = (const float4*)(p + (size_t)j * D_DIM);
    float np2 = 0.f, sxdot = 0.f;
    #pragma unroll
    for (int q = 0; q < 32; ++q) {
        float4 v = pr[q];
        float4 s = ((const float4*)g_sum_x)[q];
        np2   += v.x*v.x + v.y*v.y + v.z*v.z + v.w*v.w;
        sxdot += v.x*s.x + v.y*s.y + v.z*s.z + v.w*s.w;
        uint2 hi, lo;
        split2(v.x, v.y, hi.x, lo.x);
        split2(v.z, v.w, hi.y, lo.y);
        *(uint2*)(g_phi + (size_t)j * D_DIM + q * 4) = hi;
        *(uint2*)(g_plo + (size_t)j * D_DIM + q * 4) = lo;
    }
    float ssd    = g_sum_nx2 + (float)N_ROWS * np2 - 2.f * sxdot;
    float inv_np = rsqrtf(np2);
    float invc   = rsqrtf(np2 * ssd);
    float psi    = asinf(K_CONST * (1.f - np2) * inv_np);
    g_pstat[j]   = make_float4(np2, invc, psi, 1.f + np2);
}

// ======================= main fused kernel ===================================
// SMEM map (bytes):
#define SM_RED 0                       // 32 floats
#define SM_PS  128                     // 2 x 2048 (pstat tiles, double buffered)
#define SM_AH  4352                    // 32768
#define SM_AL  (SM_AH + 32768)         // 32768
#define SM_B   (SM_AL + 32768)         // 2 x (32768 hi + 32768 lo)
#define SMEM_TOTAL (SM_B + 2 * 65536)  // 200960

// Tile stored as [128 rows][16 chunks of 16B]; phys chunk = c ^ (row & 7).
__device__ __forceinline__ uint32_t sw_off(int row, int c) {
    return (uint32_t)(row * 256 + ((c ^ (row & 7)) << 4));
}

__device__ __forceinline__ void load_b_tile(uint32_t sb, int buf, int t) {
    const int tid = threadIdx.x;
    const uint32_t bh = sb + SM_B + buf * 65536u, bl = bh + 32768u;
    const size_t rbase = (size_t)t * 128 * D_DIM;
    #pragma unroll
    for (int i = 0; i < 8; ++i) {
        int idx = tid + i * 256;
        int row = idx >> 4, c = idx & 15;
        uint32_t off = sw_off(row, c);
        size_t src = rbase + (size_t)row * D_DIM + c * 8;
        CPA16(bh + off, (const void*)(g_phi + src));
        CPA16(bl + off, (const void*)(g_plo + src));
    }
}

// fast acos via A&S 4.4.45 (|err| <= 2e-8), sqrt.approx
__device__ __forceinline__ float acos_fast(float x) {
    float ax = fabsf(x);
    float s;
    asm("sqrt.approx.f32 %0, %1;" : "=f"(s) : "f"(1.0f - ax));
    float p = -0.0012624911f;
    p = fmaf(p, ax,  0.0066700901f);
    p = fmaf(p, ax, -0.0170881256f);
    p = fmaf(p, ax,  0.0308918810f);
    p = fmaf(p, ax, -0.0501743046f);
    p = fmaf(p, ax,  0.0889789874f);
    p = fmaf(p, ax, -0.2145988016f);
    p = fmaf(p, ax,  1.5707963050f);
    float r = s * p;
    return (x < 0.f) ? (3.14159265358979f - r) : r;
}

__global__ void __launch_bounds__(256, 1)
main_kernel(const int* __restrict__ labels) {
    extern __shared__ char smem[];
    const uint32_t sb = smem_u32(smem);
    const int tid = threadIdx.x;
    const int wid = tid >> 5, lane = tid & 31;
    const int rowBase = blockIdx.x * 128;
    const int warpRow = (wid & 3) * 32;      // 32-row slab
    const int warpCol = (wid >> 2) * 64;     // 64-col slab
    const int gid = lane >> 2, tig = lane & 3;
    const int lrow = lane & 15, side = lane >> 4, l7 = lane & 7;

    // ---- preload A (hi+lo), B tile 0, pstat tile 0 via cp.async ----
    #pragma unroll
    for (int i = 0; i < 8; ++i) {
        int idx = tid + i * 256;
        int row = idx >> 4, c = idx & 15;
        uint32_t off = sw_off(row, c);
        size_t src = (size_t)(rowBase + row) * D_DIM + c * 8;
        CPA16(sb + SM_AH + off, (const void*)(g_xhi + src));
        CPA16(sb + SM_AL + off, (const void*)(g_xlo + src));
    }
    load_b_tile(sb, 0, 0);
    if (tid < 128) CPA16(sb + SM_PS + tid * 16, (const void*)(g_pstat + tid));
    CPA_COMMIT();

    // ---- per-thread row constants (rows: warpRow + mt*16 + gid + 8h) ----
    float bx4[4], b14[4]; int lab4[4];
    #pragma unroll
    for (int mt = 0; mt < 2; ++mt)
        #pragma unroll
        for (int h = 0; h < 2; ++h) {
            int r = rowBase + warpRow + mt * 16 + gid + h * 8;
            bx4[mt * 2 + h]  = g_nx2[r];
            b14[mt * 2 + h]  = 1.f + bx4[mt * 2 + h];
            lab4[mt * 2 + h] = labels[r];
        }

    CPA_WAIT0();
    __syncthreads();

    float local = 0.f;
    for (int t = 0; t < 16; ++t) {
        const int cur = t & 1;
        if (t < 15) {
            load_b_tile(sb, cur ^ 1, t + 1);
            if (tid < 128)
                CPA16(sb + SM_PS + (cur ^ 1) * 2048u + tid * 16,
                      (const void*)(g_pstat + (t + 1) * 128 + tid));
        }
        CPA_COMMIT();

        // ---- MMA: acc = Ah*Bh + Ah*Bl + Al*Bh (fp32 accum) ----
        const uint32_t AH = sb + SM_AH, AL = sb + SM_AL;
        const uint32_t BH = sb + SM_B + cur * 65536u, BL = BH + 32768u;
        float acc[2][8][4];
        #pragma unroll
        for (int mt = 0; mt < 2; ++mt)
            #pragma unroll
            for (int nt = 0; nt < 8; ++nt)
                #pragma unroll
                for (int q = 0; q < 4; ++q) acc[mt][nt][q] = 0.f;

        #pragma unroll
        for (int ks = 0; ks < 8; ++ks) {
            const uint32_t kc = (uint32_t)(((ks * 2 + side) ^ l7) << 4);
            uint32_t ah[2][4], al[2][4];
            ldsm4(ah[0], AH + (uint32_t)(warpRow      + lrow) * 256 + kc);
            ldsm4(ah[1], AH + (uint32_t)(warpRow + 16 + lrow) * 256 + kc);
            ldsm4(al[0], AL + (uint32_t)(warpRow      + lrow) * 256 + kc);
            ldsm4(al[1], AL + (uint32_t)(warpRow + 16 + lrow) * 256 + kc);
            #pragma unroll
            for (int tp = 0; tp < 4; ++tp) {
                uint32_t bh[4], bl[4];
                uint32_t boff = (uint32_t)(warpCol + tp * 16 + lrow) * 256 + kc;
                ldsm4(bh, BH + boff);
                ldsm4(bl, BL + boff);
                #pragma unroll
                for (int mt = 0; mt < 2; ++mt) {
                    mma16816(acc[mt][tp*2],   ah[mt], bh[0], bh[2]);
                    mma16816(acc[mt][tp*2+1], ah[mt], bh[1], bh[3]);
                    mma16816(acc[mt][tp*2],   ah[mt], bl[0], bl[2]);
                    mma16816(acc[mt][tp*2+1], ah[mt], bl[1], bl[3]);
                    mma16816(acc[mt][tp*2],   al[mt], bh[0], bh[2]);
                    mma16816(acc[mt][tp*2+1], al[mt], bh[1], bh[3]);
                }
            }
        }

        // ---- epilogue on registers ----
        const float4* pss = (const float4*)(smem + SM_PS + cur * 2048);
        const int colBase = t * 128 + warpCol;
        #pragma unroll
        for (int nt = 0; nt < 8; ++nt) {
            const float4 ps0 = pss[(warpCol >> 1) + nt * 4 + tig * 2 - (warpCol >> 1) + 0];
            const float4 ps1 = pss[nt * 8 + tig * 2 + 1];
            const float4 psA = pss[nt * 8 + tig * 2];
            const int col0 = colBase + nt * 8 + tig * 2;
            #pragma unroll
            for (int mt = 0; mt < 2; ++mt)
                #pragma unroll
                for (int h = 0; h < 2; ++h) {
                    const int   ri  = mt * 2 + h;
                    const float bxv = bx4[ri], b1v = b14[ri];
                    const int   rl  = lab4[ri];
                    #pragma unroll
                    for (int e = 0; e < 2; ++e) {
                        const float4 ps = e ? ps1 : psA;
                        float dot   = acc[mt][nt][h * 2 + e];
                        float num   = fmaf(dot, ps.w, -ps.x * b1v);
                        float tt    = fmaf(-2.f, dot, fmaf(ps.x, bxv, 1.f));
                        float ratio = num * ps.y * rsqrtf(tt);
                        ratio       = fminf(1.f, fmaxf(-1.f, ratio));
                        float angle = acos_fast(ratio);
                        float ang   = fmaxf(0.f, angle - ps.z);
                        float hinge = fmaxf(0.f, GAMMA_CONST - ang);
                        local += hinge;
                        if (col0 + e == rl) local += ang - hinge;
                    }
                }
            (void)ps0;
        }

        CPA_WAIT0();
        __syncthreads();
    }

    // ---- block reduction -> one double atomic per CTA ----
    #pragma unroll
    for (int o = 16; o; o >>= 1) local += __shfl_xor_sync(0xffffffffu, local, o);
    float* red = (float*)(smem + SM_RED);
    if (lane == 0) red[wid] = local;
    __syncthreads();
    if (tid == 0) {
        float s = 0.f;
        #pragma unroll
        for (int w = 0; w < 8; ++w) s += red[w];
        atomicAdd(&g_acc, (double)s);
    }
}

__global__ void finish_kernel(float* __restrict__ out) {
    out[0] = (float)(g_acc / (double)N_ROWS);
}

// ======================= launch ==============================================
extern "C" void kernel_launch(void* const* d_in, const int* in_sizes, int n_in,
                              void* d_out, int out_size) {
    const float* x      = (const float*)d_in[0];
    const float* p      = (const float*)d_in[1];
    const int*   labels = (const int*)d_in[2];
    float* out = (float*)d_out;

    cudaFuncSetAttribute(main_kernel, cudaFuncAttributeMaxDynamicSharedMemorySize, SMEM_TOTAL);

    init_kernel<<<1, 128>>>();
    xstats_kernel<<<256, 256>>>(x);
    pstats_kernel<<<8, 256>>>(p);
    main_kernel<<<128, 256, SMEM_TOTAL>>>(labels);
    finish_kernel<<<1, 1>>>(out);
}

// round 6
// speedup vs baseline: 2.7699x; 1.1043x over previous
#include <cuda_runtime.h>
#include <cuda_bf16.h>
#include <cstdint>

#define N_ROWS 16384
#define M_COLS 2048
#define D_DIM  128
#define K_CONST 0.1f
#define GAMMA_CONST 1.0f

// ======================= PTX helpers ========================================
__device__ __forceinline__ uint32_t smem_u32(const void* p) {
    uint32_t a;
    asm("{ .reg .u64 t; cvta.to.shared.u64 t, %1; cvt.u32.u64 %0, t; }" : "=r"(a) : "l"(p));
    return a;
}
#define CPA16(dst, src) \
    asm volatile("cp.async.cg.shared.global [%0], [%1], 16;" :: "r"(dst), "l"(src))
#define CPA_COMMIT() asm volatile("cp.async.commit_group;" ::: "memory")
#define CPA_WAIT0()  asm volatile("cp.async.wait_group 0;" ::: "memory")

__device__ __forceinline__ void ldsm4(uint32_t* r, uint32_t addr) {
    asm volatile("ldmatrix.sync.aligned.m8n8.x4.shared.b16 {%0,%1,%2,%3}, [%4];"
        : "=r"(r[0]), "=r"(r[1]), "=r"(r[2]), "=r"(r[3]) : "r"(addr));
}
__device__ __forceinline__ void mma16816(float* c, const uint32_t* a, uint32_t b0, uint32_t b1) {
    asm volatile("mma.sync.aligned.m16n8k16.row.col.f32.bf16.bf16.f32 "
        "{%0,%1,%2,%3}, {%4,%5,%6,%7}, {%8,%9}, {%0,%1,%2,%3};"
        : "+f"(c[0]), "+f"(c[1]), "+f"(c[2]), "+f"(c[3])
        : "r"(a[0]), "r"(a[1]), "r"(a[2]), "r"(a[3]), "r"(b0), "r"(b1));
}

// ======================= scratch device globals ==============================
__device__ __align__(16) __nv_bfloat16 g_xhi[N_ROWS * D_DIM];
__device__ __align__(16) __nv_bfloat16 g_xlo[N_ROWS * D_DIM];
__device__ __align__(16) __nv_bfloat16 g_phi[M_COLS * D_DIM];
__device__ __align__(16) __nv_bfloat16 g_plo[M_COLS * D_DIM];
__device__ float  g_sum_x[D_DIM];
__device__ float  g_sum_nx2;
__device__ float  g_nx2[N_ROWS];
__device__ float4 g_pstat[M_COLS];   // {np2, 1/(||p||*sqrt(ssd)), psi, 1+np2}
__device__ double g_acc;

// ======================= prep kernels ========================================
__global__ void init_kernel() {
    int t = threadIdx.x;
    if (t < D_DIM) g_sum_x[t] = 0.f;
    if (t == 0) { g_sum_nx2 = 0.f; g_acc = 0.0; }
}

__device__ __forceinline__ void split2(float a, float b, uint32_t& hi, uint32_t& lo) {
    __nv_bfloat162 h = __floats2bfloat162_rn(a, b);
    float ra = a - __bfloat162float(__low2bfloat16(h));
    float rb = b - __bfloat162float(__high2bfloat16(h));
    __nv_bfloat162 l = __floats2bfloat162_rn(ra, rb);
    hi = *(uint32_t*)&h; lo = *(uint32_t*)&l;
}

__global__ void xstats_kernel(const float* __restrict__ x) {
    int lane = threadIdx.x & 31;
    int wid  = threadIdx.x >> 5;
    int base = (blockIdx.x * 8 + wid) * 8;

    float sx0 = 0.f, sx1 = 0.f, sx2 = 0.f, sx3 = 0.f;
    float snx2 = 0.f;
    #pragma unroll
    for (int rr = 0; rr < 8; ++rr) {
        int row = base + rr;
        float4 v = ((const float4*)(x + (size_t)row * D_DIM))[lane];
        uint2 hi, lo;
        split2(v.x, v.y, hi.x, lo.x);
        split2(v.z, v.w, hi.y, lo.y);
        *(uint2*)(g_xhi + (size_t)row * D_DIM + lane * 4) = hi;
        *(uint2*)(g_xlo + (size_t)row * D_DIM + lane * 4) = lo;
        float d = v.x*v.x + v.y*v.y + v.z*v.z + v.w*v.w;
        snx2 += d;
        float dr = d;
        #pragma unroll
        for (int o = 16; o; o >>= 1) dr += __shfl_xor_sync(0xffffffffu, dr, o);
        if (lane == 0) g_nx2[row] = dr;
        sx0 += v.x; sx1 += v.y; sx2 += v.z; sx3 += v.w;
    }
    atomicAdd(&g_sum_x[lane*4+0], sx0);
    atomicAdd(&g_sum_x[lane*4+1], sx1);
    atomicAdd(&g_sum_x[lane*4+2], sx2);
    atomicAdd(&g_sum_x[lane*4+3], sx3);
    #pragma unroll
    for (int o = 16; o; o >>= 1) snx2 += __shfl_xor_sync(0xffffffffu, snx2, o);
    if (lane == 0) atomicAdd(&g_sum_nx2, snx2);
}

// warp-per-column: lane owns 4 dims, coalesced split writes
__global__ void pstats_kernel(const float* __restrict__ p) {
    int j    = blockIdx.x * 8 + (threadIdx.x >> 5);
    int lane = threadIdx.x & 31;
    if (j >= M_COLS) return;
    float4 v = ((const float4*)(p + (size_t)j * D_DIM))[lane];
    float4 s = ((const float4*)g_sum_x)[lane];
    float np2   = v.x*v.x + v.y*v.y + v.z*v.z + v.w*v.w;
    float sxdot = v.x*s.x + v.y*s.y + v.z*s.z + v.w*s.w;
    uint2 hi, lo;
    split2(v.x, v.y, hi.x, lo.x);
    split2(v.z, v.w, hi.y, lo.y);
    *(uint2*)(g_phi + (size_t)j * D_DIM + lane * 4) = hi;
    *(uint2*)(g_plo + (size_t)j * D_DIM + lane * 4) = lo;
    #pragma unroll
    for (int o = 16; o; o >>= 1) {
        np2   += __shfl_xor_sync(0xffffffffu, np2, o);
        sxdot += __shfl_xor_sync(0xffffffffu, sxdot, o);
    }
    if (lane == 0) {
        float ssd    = g_sum_nx2 + (float)N_ROWS * np2 - 2.f * sxdot;
        float inv_np = rsqrtf(np2);
        float invc   = rsqrtf(np2 * ssd);
        float psi    = asinf(K_CONST * (1.f - np2) * inv_np);
        g_pstat[j]   = make_float4(np2, invc, psi, 1.f + np2);
    }
}

// ======================= main fused kernel ===================================
// SMEM map (bytes):
#define SM_RED 0                       // 16 floats
#define SM_PS  128                     // 2 x 2048 (pstat tiles, double buffered)
#define SM_AH  4352                    // 32768
#define SM_AL  (SM_AH + 32768)         // 32768
#define SM_B   (SM_AL + 32768)         // 2 x (32768 hi + 32768 lo)
#define SMEM_TOTAL (SM_B + 2 * 65536)  // 200960
#define NTHREADS 512

// Tile stored as [128 rows][16 chunks of 16B]; phys chunk = c ^ (row & 7).
__device__ __forceinline__ uint32_t sw_off(int row, int c) {
    return (uint32_t)(row * 256 + ((c ^ (row & 7)) << 4));
}

__device__ __forceinline__ void load_b_tile(uint32_t sb, int buf, int t) {
    const int tid = threadIdx.x;
    const uint32_t bh = sb + SM_B + buf * 65536u, bl = bh + 32768u;
    const size_t rbase = (size_t)t * 128 * D_DIM;
    #pragma unroll
    for (int i = 0; i < 4; ++i) {
        int idx = tid + i * NTHREADS;
        int row = idx >> 4, c = idx & 15;
        uint32_t off = sw_off(row, c);
        size_t src = rbase + (size_t)row * D_DIM + c * 8;
        CPA16(bh + off, (const void*)(g_phi + src));
        CPA16(bl + off, (const void*)(g_plo + src));
    }
}

// fast acos via A&S 4.4.45 (|err| <= 2e-8), sqrt.approx
__device__ __forceinline__ float acos_fast(float x) {
    float ax = fabsf(x);
    float s;
    asm("sqrt.approx.f32 %0, %1;" : "=f"(s) : "f"(1.0f - ax));
    float p = -0.0012624911f;
    p = fmaf(p, ax,  0.0066700901f);
    p = fmaf(p, ax, -0.0170881256f);
    p = fmaf(p, ax,  0.0308918810f);
    p = fmaf(p, ax, -0.0501743046f);
    p = fmaf(p, ax,  0.0889789874f);
    p = fmaf(p, ax, -0.2145988016f);
    p = fmaf(p, ax,  1.5707963050f);
    float r = s * p;
    return (x < 0.f) ? (3.14159265358979f - r) : r;
}

__global__ void __launch_bounds__(NTHREADS, 1)
main_kernel(const int* __restrict__ labels) {
    extern __shared__ char smem[];
    const uint32_t sb = smem_u32(smem);
    const int tid = threadIdx.x;
    const int wid = tid >> 5, lane = tid & 31;
    const int rowBase = blockIdx.x * 128;
    const int warpRow = (wid & 3) * 32;      // 32-row slab
    const int warpCol = (wid >> 2) * 32;     // 32-col slab (16 warps: 4x4)
    const int gid = lane >> 2, tig = lane & 3;
    const int lrow = lane & 15, side = lane >> 4, l7 = lane & 7;

    // ---- preload A (hi+lo), B tile 0, pstat tile 0 via cp.async ----
    #pragma unroll
    for (int i = 0; i < 4; ++i) {
        int idx = tid + i * NTHREADS;
        int row = idx >> 4, c = idx & 15;
        uint32_t off = sw_off(row, c);
        size_t src = (size_t)(rowBase + row) * D_DIM + c * 8;
        CPA16(sb + SM_AH + off, (const void*)(g_xhi + src));
        CPA16(sb + SM_AL + off, (const void*)(g_xlo + src));
    }
    load_b_tile(sb, 0, 0);
    if (tid < 128) CPA16(sb + SM_PS + tid * 16, (const void*)(g_pstat + tid));
    CPA_COMMIT();

    // ---- per-thread row constants (rows: warpRow + mt*16 + gid + 8h) ----
    float bx4[4], b14[4]; int lab4[4];
    #pragma unroll
    for (int mt = 0; mt < 2; ++mt)
        #pragma unroll
        for (int h = 0; h < 2; ++h) {
            int r = rowBase + warpRow + mt * 16 + gid + h * 8;
            bx4[mt * 2 + h]  = g_nx2[r];
            b14[mt * 2 + h]  = 1.f + bx4[mt * 2 + h];
            lab4[mt * 2 + h] = labels[r];
        }

    CPA_WAIT0();
    __syncthreads();

    float local = 0.f;
    for (int t = 0; t < 16; ++t) {
        const int cur = t & 1;
        if (t < 15) {
            load_b_tile(sb, cur ^ 1, t + 1);
            if (tid < 128)
                CPA16(sb + SM_PS + (cur ^ 1) * 2048u + tid * 16,
                      (const void*)(g_pstat + (t + 1) * 128 + tid));
        }
        CPA_COMMIT();

        // ---- MMA: acc = Ah*Bh + Ah*Bl + Al*Bh (fp32 accum) ----
        const uint32_t AH = sb + SM_AH, AL = sb + SM_AL;
        const uint32_t BH = sb + SM_B + cur * 65536u, BL = BH + 32768u;
        float acc[2][4][4];
        #pragma unroll
        for (int mt = 0; mt < 2; ++mt)
            #pragma unroll
            for (int nt = 0; nt < 4; ++nt)
                #pragma unroll
                for (int q = 0; q < 4; ++q) acc[mt][nt][q] = 0.f;

        #pragma unroll
        for (int ks = 0; ks < 8; ++ks) {
            const uint32_t kc = (uint32_t)(((ks * 2 + side) ^ l7) << 4);
            uint32_t ah[2][4], al[2][4];
            ldsm4(ah[0], AH + (uint32_t)(warpRow      + lrow) * 256 + kc);
            ldsm4(ah[1], AH + (uint32_t)(warpRow + 16 + lrow) * 256 + kc);
            ldsm4(al[0], AL + (uint32_t)(warpRow      + lrow) * 256 + kc);
            ldsm4(al[1], AL + (uint32_t)(warpRow + 16 + lrow) * 256 + kc);
            #pragma unroll
            for (int tp = 0; tp < 2; ++tp) {
                uint32_t bh[4], bl[4];
                uint32_t boff = (uint32_t)(warpCol + tp * 16 + lrow) * 256 + kc;
                ldsm4(bh, BH + boff);
                ldsm4(bl, BL + boff);
                #pragma unroll
                for (int mt = 0; mt < 2; ++mt) {
                    mma16816(acc[mt][tp*2],   ah[mt], bh[0], bh[2]);
                    mma16816(acc[mt][tp*2+1], ah[mt], bh[1], bh[3]);
                    mma16816(acc[mt][tp*2],   ah[mt], bl[0], bl[2]);
                    mma16816(acc[mt][tp*2+1], ah[mt], bl[1], bl[3]);
                    mma16816(acc[mt][tp*2],   al[mt], bh[0], bh[2]);
                    mma16816(acc[mt][tp*2+1], al[mt], bh[1], bh[3]);
                }
            }
        }

        // ---- epilogue on registers ----
        const float4* pss = (const float4*)(smem + SM_PS + cur * 2048);
        const int colBase = t * 128 + warpCol;
        #pragma unroll
        for (int nt = 0; nt < 4; ++nt) {
            const float4 psA = pss[warpCol + nt * 8 + tig * 2];
            const float4 ps1 = pss[warpCol + nt * 8 + tig * 2 + 1];
            const int col0 = colBase + nt * 8 + tig * 2;
            #pragma unroll
            for (int mt = 0; mt < 2; ++mt)
                #pragma unroll
                for (int h = 0; h < 2; ++h) {
                    const int   ri  = mt * 2 + h;
                    const float bxv = bx4[ri], b1v = b14[ri];
                    const int   rl  = lab4[ri];
                    #pragma unroll
                    for (int e = 0; e < 2; ++e) {
                        const float4 ps = e ? ps1 : psA;
                        float dot   = acc[mt][nt][h * 2 + e];
                        float num   = fmaf(dot, ps.w, -ps.x * b1v);
                        float tt    = fmaf(-2.f, dot, fmaf(ps.x, bxv, 1.f));
                        float ratio = num * ps.y * rsqrtf(tt);
                        ratio       = fminf(1.f, fmaxf(-1.f, ratio));
                        float angle = acos_fast(ratio);
                        float ang   = fmaxf(0.f, angle - ps.z);
                        float hinge = fmaxf(0.f, GAMMA_CONST - ang);
                        local += hinge;
                        if (col0 + e == rl) local += ang - hinge;
                    }
                }
        }

        CPA_WAIT0();
        __syncthreads();
    }

    // ---- block reduction -> one double atomic per CTA ----
    #pragma unroll
    for (int o = 16; o; o >>= 1) local += __shfl_xor_sync(0xffffffffu, local, o);
    float* red = (float*)(smem + SM_RED);
    if (lane == 0) red[wid] = local;
    __syncthreads();
    if (tid == 0) {
        float s = 0.f;
        #pragma unroll
        for (int w = 0; w < 16; ++w) s += red[w];
        atomicAdd(&g_acc, (double)s);
    }
}

__global__ void finish_kernel(float* __restrict__ out) {
    out[0] = (float)(g_acc / (double)N_ROWS);
}

// ======================= launch ==============================================
extern "C" void kernel_launch(void* const* d_in, const int* in_sizes, int n_in,
                              void* d_out, int out_size) {
    const float* x      = (const float*)d_in[0];
    const float* p      = (const float*)d_in[1];
    const int*   labels = (const int*)d_in[2];
    float* out = (float*)d_out;

    cudaFuncSetAttribute(main_kernel, cudaFuncAttributeMaxDynamicSharedMemorySize, SMEM_TOTAL);

    init_kernel<<<1, 128>>>();
    xstats_kernel<<<256, 256>>>(x);
    pstats_kernel<<<256, 256>>>(p);
    main_kernel<<<128, NTHREADS, SMEM_TOTAL>>>(labels);
    finish_kernel<<<1, 1>>>(out);
}

// round 9
// speedup vs baseline: 2.9989x; 1.0827x over previous
#include <cuda_runtime.h>
#include <cuda_bf16.h>
#include <cstdint>

#define N_ROWS 16384
#define M_COLS 2048
#define D_DIM  128
#define K_CONST 0.1f
#define GAMMA_CONST 1.0f

// ======================= PTX helpers ========================================
__device__ __forceinline__ uint32_t smem_u32(const void* p) {
    uint32_t a;
    asm("{ .reg .u64 t; cvta.to.shared.u64 t, %1; cvt.u32.u64 %0, t; }" : "=r"(a) : "l"(p));
    return a;
}
#define CPA16(dst, src) \
    asm volatile("cp.async.cg.shared.global [%0], [%1], 16;" :: "r"(dst), "l"(src))
#define CPA_COMMIT() asm volatile("cp.async.commit_group;" ::: "memory")
#define CPA_WAIT0()  asm volatile("cp.async.wait_group 0;" ::: "memory")

__device__ __forceinline__ void ldsm4(uint32_t* r, uint32_t addr) {
    asm volatile("ldmatrix.sync.aligned.m8n8.x4.shared.b16 {%0,%1,%2,%3}, [%4];"
        : "=r"(r[0]), "=r"(r[1]), "=r"(r[2]), "=r"(r[3]) : "r"(addr));
}
__device__ __forceinline__ void mma16816(float* c, const uint32_t* a, uint32_t b0, uint32_t b1) {
    asm volatile("mma.sync.aligned.m16n8k16.row.col.f32.bf16.bf16.f32 "
        "{%0,%1,%2,%3}, {%4,%5,%6,%7}, {%8,%9}, {%0,%1,%2,%3};"
        : "+f"(c[0]), "+f"(c[1]), "+f"(c[2]), "+f"(c[3])
        : "r"(a[0]), "r"(a[1]), "r"(a[2]), "r"(a[3]), "r"(b0), "r"(b1));
}

// ======================= scratch device globals ==============================
__device__ __align__(16) __nv_bfloat16 g_phi[M_COLS * D_DIM];
__device__ __align__(16) __nv_bfloat16 g_plo[M_COLS * D_DIM];
__device__ float  g_sum_x[D_DIM];
__device__ float  g_sum_nx2;
__device__ float  g_nx2[N_ROWS];
__device__ float4 g_pstat[M_COLS];   // {np2, 1/(||p||*sqrt(ssd)), psi, cos(G+psi)}
__device__ double g_acc;

// ======================= prep kernels ========================================
__global__ void init_kernel() {
    int t = threadIdx.x;
    if (t < D_DIM) g_sum_x[t] = 0.f;
    if (t == 0) { g_sum_nx2 = 0.f; g_acc = 0.0; }
}

__device__ __forceinline__ void split2(float a, float b, uint32_t& hi, uint32_t& lo) {
    __nv_bfloat162 h = __floats2bfloat162_rn(a, b);
    float ra = a - __bfloat162float(__low2bfloat16(h));
    float rb = b - __bfloat162float(__high2bfloat16(h));
    __nv_bfloat162 l = __floats2bfloat162_rn(ra, rb);
    hi = *(uint32_t*)&h; lo = *(uint32_t*)&l;
}

// per-row ||x||^2 + column sums
__global__ void xstats_kernel(const float* __restrict__ x) {
    int lane = threadIdx.x & 31;
    int wid  = threadIdx.x >> 5;
    int base = (blockIdx.x * 8 + wid) * 8;

    float sx0 = 0.f, sx1 = 0.f, sx2 = 0.f, sx3 = 0.f;
    float snx2 = 0.f;
    #pragma unroll
    for (int rr = 0; rr < 8; ++rr) {
        int row = base + rr;
        float4 v = ((const float4*)(x + (size_t)row * D_DIM))[lane];
        float d = v.x*v.x + v.y*v.y + v.z*v.z + v.w*v.w;
        snx2 += d;
        float dr = d;
        #pragma unroll
        for (int o = 16; o; o >>= 1) dr += __shfl_xor_sync(0xffffffffu, dr, o);
        if (lane == 0) g_nx2[row] = dr;
        sx0 += v.x; sx1 += v.y; sx2 += v.z; sx3 += v.w;
    }
    atomicAdd(&g_sum_x[lane*4+0], sx0);
    atomicAdd(&g_sum_x[lane*4+1], sx1);
    atomicAdd(&g_sum_x[lane*4+2], sx2);
    atomicAdd(&g_sum_x[lane*4+3], sx3);
    #pragma unroll
    for (int o = 16; o; o >>= 1) snx2 += __shfl_xor_sync(0xffffffffu, snx2, o);
    if (lane == 0) atomicAdd(&g_sum_nx2, snx2);
}

// warp-per-column: lane owns 4 dims, coalesced split writes
__global__ void pstats_kernel(const float* __restrict__ p) {
    int j    = blockIdx.x * 8 + (threadIdx.x >> 5);
    int lane = threadIdx.x & 31;
    if (j >= M_COLS) return;
    float4 v = ((const float4*)(p + (size_t)j * D_DIM))[lane];
    float4 s = ((const float4*)g_sum_x)[lane];
    float np2   = v.x*v.x + v.y*v.y + v.z*v.z + v.w*v.w;
    float sxdot = v.x*s.x + v.y*s.y + v.z*s.z + v.w*s.w;
    uint2 hi, lo;
    split2(v.x, v.y, hi.x, lo.x);
    split2(v.z, v.w, hi.y, lo.y);
    *(uint2*)(g_phi + (size_t)j * D_DIM + lane * 4) = hi;
    *(uint2*)(g_plo + (size_t)j * D_DIM + lane * 4) = lo;
    #pragma unroll
    for (int o = 16; o; o >>= 1) {
        np2   += __shfl_xor_sync(0xffffffffu, np2, o);
        sxdot += __shfl_xor_sync(0xffffffffu, sxdot, o);
    }
    if (lane == 0) {
        float ssd    = g_sum_nx2 + (float)N_ROWS * np2 - 2.f * sxdot;
        float inv_np = rsqrtf(np2);
        float invc   = rsqrtf(np2 * ssd);
        float psi    = asinf(K_CONST * (1.f - np2) * inv_np);
        float c1     = cosf(GAMMA_CONST + psi);   // zero-contribution threshold
        g_pstat[j]   = make_float4(np2, invc, psi, c1);
    }
}

// ======================= main fused kernel ===================================
// SMEM map (bytes):
#define SM_RED 0                       // 16 floats + pad
#define SM_PS  128                     // full pstat: 2048 * 16 = 32768
#define SM_AH  (SM_PS + 32768)         // 32768
#define SM_AL  (SM_AH + 32768)         // 32768
#define SM_B   (SM_AL + 32768)         // 2 x (32768 hi + 32768 lo) = 131072
#define SMEM_TOTAL (SM_B + 2 * 65536)  // 229504
#define NTHREADS 512

// Tile stored as [128 rows][16 chunks of 16B]; phys chunk = c ^ (row & 7).
__device__ __forceinline__ uint32_t sw_off(int row, int c) {
    return (uint32_t)(row * 256 + ((c ^ (row & 7)) << 4));
}

__device__ __forceinline__ void load_b_tile(uint32_t sb, int buf, int t) {
    const int tid = threadIdx.x;
    const uint32_t bh = sb + SM_B + buf * 65536u, bl = bh + 32768u;
    const size_t rbase = (size_t)t * 128 * D_DIM;
    #pragma unroll
    for (int i = 0; i < 4; ++i) {
        int idx = tid + i * NTHREADS;
        int row = idx >> 4, c = idx & 15;
        uint32_t off = sw_off(row, c);
        size_t src = rbase + (size_t)row * D_DIM + c * 8;
        CPA16(bh + off, (const void*)(g_phi + src));
        CPA16(bl + off, (const void*)(g_plo + src));
    }
}

// fast acos via A&S 4.4.45 (|err| <= 2e-8), sqrt.approx
__device__ __forceinline__ float acos_fast(float x) {
    float ax = fabsf(x);
    float s;
    asm("sqrt.approx.f32 %0, %1;" : "=f"(s) : "f"(1.0f - ax));
    float p = -0.0012624911f;
    p = fmaf(p, ax,  0.0066700901f);
    p = fmaf(p, ax, -0.0170881256f);
    p = fmaf(p, ax,  0.0308918810f);
    p = fmaf(p, ax, -0.0501743046f);
    p = fmaf(p, ax,  0.0889789874f);
    p = fmaf(p, ax, -0.2145988016f);
    p = fmaf(p, ax,  1.5707963050f);
    float r = s * p;
    return (x < 0.f) ? (3.14159265358979f - r) : r;
}

__global__ void __launch_bounds__(NTHREADS, 1)
main_kernel(const float* __restrict__ x, const int* __restrict__ labels) {
    extern __shared__ char smem[];
    const uint32_t sb = smem_u32(smem);
    const int tid = threadIdx.x;
    const int wid = tid >> 5, lane = tid & 31;
    const int rowBase = blockIdx.x * 128;
    const int warpRow = (wid & 3) * 32;      // 32-row slab
    const int warpCol = (wid >> 2) * 32;     // 32-col slab (16 warps: 4x4)
    const int gid = lane >> 2, tig = lane & 3;
    const int lrow = lane & 15, side = lane >> 4, l7 = lane & 7;

    // ---- async loads: full pstat (32KB), B tiles 0 and 1 ----
    #pragma unroll
    for (int i = 0; i < 4; ++i) {
        int idx = tid + i * NTHREADS;
        CPA16(sb + SM_PS + idx * 16, (const void*)(g_pstat + idx));
    }
    load_b_tile(sb, 0, 0);
    load_b_tile(sb, 1, 1);
    CPA_COMMIT();

    // ---- A: load fp32 x tile, split to bf16 hi/lo in smem ----
    #pragma unroll
    for (int i = 0; i < 4; ++i) {
        int idx = tid + i * NTHREADS;          // 2048 16B-chunks
        int row = idx >> 4, c = idx & 15;
        const float4* src = (const float4*)(x + (size_t)(rowBase + row) * D_DIM + c * 8);
        float4 a = src[0], b = src[1];
        uint4 h, l;
        split2(a.x, a.y, h.x, l.x);
        split2(a.z, a.w, h.y, l.y);
        split2(b.x, b.y, h.z, l.z);
        split2(b.z, b.w, h.w, l.w);
        uint32_t off = sw_off(row, c);
        *(uint4*)(smem + SM_AH + off) = h;
        *(uint4*)(smem + SM_AL + off) = l;
    }

    // ---- per-thread row constants ----
    float bx4[4]; int lab4[4];
    #pragma unroll
    for (int mt = 0; mt < 2; ++mt)
        #pragma unroll
        for (int h = 0; h < 2; ++h) {
            int r = rowBase + warpRow + mt * 16 + gid + h * 8;
            bx4[mt * 2 + h]  = g_nx2[r];
            lab4[mt * 2 + h] = labels[r];
        }

    CPA_WAIT0();
    __syncthreads();

    const uint32_t AH = sb + SM_AH, AL = sb + SM_AL;
    const float4* pss = (const float4*)(smem + SM_PS);

    float acc[2][2][4][4];   // [bank][mt][nt][q]
    float local = 0.f;

    // ---- MMA for one tile from buffer `buf` into bank `pb` ----
    auto mma_tile = [&](int buf, int pb) {
        const uint32_t BH = sb + SM_B + buf * 65536u, BL = BH + 32768u;
        #pragma unroll
        for (int mt = 0; mt < 2; ++mt)
            #pragma unroll
            for (int nt = 0; nt < 4; ++nt)
                #pragma unroll
                for (int q = 0; q < 4; ++q) acc[pb][mt][nt][q] = 0.f;
        #pragma unroll
        for (int ks = 0; ks < 8; ++ks) {
            const uint32_t kc = (uint32_t)(((ks * 2 + side) ^ l7) << 4);
            uint32_t ah[2][4], al[2][4];
            ldsm4(ah[0], AH + (uint32_t)(warpRow      + lrow) * 256 + kc);
            ldsm4(ah[1], AH + (uint32_t)(warpRow + 16 + lrow) * 256 + kc);
            ldsm4(al[0], AL + (uint32_t)(warpRow      + lrow) * 256 + kc);
            ldsm4(al[1], AL + (uint32_t)(warpRow + 16 + lrow) * 256 + kc);
            #pragma unroll
            for (int tp = 0; tp < 2; ++tp) {
                uint32_t bh[4], bl[4];
                uint32_t boff = (uint32_t)(warpCol + tp * 16 + lrow) * 256 + kc;
                ldsm4(bh, BH + boff);
                ldsm4(bl, BL + boff);
                #pragma unroll
                for (int mt = 0; mt < 2; ++mt) {
                    mma16816(acc[pb][mt][tp*2],   ah[mt], bh[0], bh[2]);
                    mma16816(acc[pb][mt][tp*2+1], ah[mt], bh[1], bh[3]);
                    mma16816(acc[pb][mt][tp*2],   ah[mt], bl[0], bl[2]);
                    mma16816(acc[pb][mt][tp*2+1], ah[mt], bl[1], bl[3]);
                    mma16816(acc[pb][mt][tp*2],   al[mt], bh[0], bh[2]);
                    mma16816(acc[pb][mt][tp*2+1], al[mt], bh[1], bh[3]);
                }
            }
        }
    };

    // ---- epilogue for tile t from bank pb ----
    auto epilogue = [&](int t, int pb) {
        const int colBase = t * 128 + warpCol;
        #pragma unroll
        for (int nt = 0; nt < 4; ++nt) {
            const int ci = colBase + nt * 8 + tig * 2;
            const float4 psA = pss[ci];
            const float4 ps1 = pss[ci + 1];
            #pragma unroll
            for (int mt = 0; mt < 2; ++mt)
                #pragma unroll
                for (int h = 0; h < 2; ++h) {
                    const int   ri  = mt * 2 + h;
                    const float bxv = bx4[ri];
                    const float b1v = 1.f + bxv;
                    const int   rl  = lab4[ri];
                    #pragma unroll
                    for (int e = 0; e < 2; ++e) {
                        const float4 ps = e ? ps1 : psA;
                        float dot   = acc[pb][mt][nt][h * 2 + e];
                        float num   = fmaf(ps.x, dot - b1v, dot);       // dot(1+np2)-np2(1+nx2)
                        float tt    = fmaf(-2.f, dot, fmaf(ps.x, bxv, 1.f));
                        float ratio = num * ps.y * rsqrtf(tt);
                        bool  isl   = (ci + e == rl);
                        if (ratio > ps.w || isl) {                      // else contribution = 0
                            float rc    = fminf(1.f, fmaxf(-1.f, ratio));
                            float angle = acos_fast(rc);
                            float ang   = fmaxf(0.f, angle - ps.z);
                            float hinge = fmaxf(0.f, GAMMA_CONST - ang);
                            local += isl ? ang : hinge;
                        }
                    }
                }
        }
    };

    // ---- pipelined loop: MMA(t+1) issued before epilogue(t) ----
    mma_tile(0, 0);
    for (int tb = 0; tb < 16; tb += 2) {
        #pragma unroll
        for (int u = 0; u < 2; ++u) {
            const int t = tb + u;
            if (t < 15) {
                CPA_WAIT0();
                __syncthreads();
                if (t < 14) { load_b_tile(sb, t & 1, t + 2); CPA_COMMIT(); }
                mma_tile((t + 1) & 1, (u + 1) & 1);
            }
            epilogue(t, u);
        }
    }

    // ---- block reduction -> one double atomic per CTA ----
    #pragma unroll
    for (int o = 16; o; o >>= 1) local += __shfl_xor_sync(0xffffffffu, local, o);
    float* red = (float*)(smem + SM_RED);
    if (lane == 0) red[wid] = local;
    __syncthreads();
    if (tid == 0) {
        float s = 0.f;
        #pragma unroll
        for (int w = 0; w < 16; ++w) s += red[w];
        atomicAdd(&g_acc, (double)s);
    }
}

__global__ void finish_kernel(float* __restrict__ out) {
    out[0] = (float)(g_acc / (double)N_ROWS);
}

// ======================= launch ==============================================
extern "C" void kernel_launch(void* const* d_in, const int* in_sizes, int n_in,
                              void* d_out, int out_size) {
    const float* x      = (const float*)d_in[0];
    const float* p      = (const float*)d_in[1];
    const int*   labels = (const int*)d_in[2];
    float* out = (float*)d_out;

    cudaFuncSetAttribute(main_kernel, cudaFuncAttributeMaxDynamicSharedMemorySize, SMEM_TOTAL);

    init_kernel<<<1, 128>>>();
    xstats_kernel<<<256, 256>>>(x);
    pstats_kernel<<<256, 256>>>(p);
    main_kernel<<<128, NTHREADS, SMEM_TOTAL>>>(x, labels);
    finish_kernel<<<1, 1>>>(out);
}

// round 10
// speedup vs baseline: 6.7629x; 2.2551x over previous
#include <cuda_runtime.h>
#include <cuda_bf16.h>
#include <cstdint>

#define N_ROWS 16384
#define M_COLS 2048
#define D_DIM  128
#define K_CONST 0.1f
#define GAMMA_CONST 1.0f

// ======================= PTX helpers ========================================
__device__ __forceinline__ uint32_t smem_u32(const void* p) {
    uint32_t a;
    asm("{ .reg .u64 t; cvta.to.shared.u64 t, %1; cvt.u32.u64 %0, t; }" : "=r"(a) : "l"(p));
    return a;
}
#define CPA16(dst, src) \
    asm volatile("cp.async.cg.shared.global [%0], [%1], 16;" :: "r"(dst), "l"(src))
#define CPA_COMMIT() asm volatile("cp.async.commit_group;" ::: "memory")
#define CPA_WAIT0()  asm volatile("cp.async.wait_group 0;" ::: "memory")

__device__ __forceinline__ void ldsm4(uint32_t* r, uint32_t addr) {
    asm volatile("ldmatrix.sync.aligned.m8n8.x4.shared.b16 {%0,%1,%2,%3}, [%4];"
        : "=r"(r[0]), "=r"(r[1]), "=r"(r[2]), "=r"(r[3]) : "r"(addr));
}
__device__ __forceinline__ void mma16816(float* c, const uint32_t* a, uint32_t b0, uint32_t b1) {
    asm volatile("mma.sync.aligned.m16n8k16.row.col.f32.bf16.bf16.f32 "
        "{%0,%1,%2,%3}, {%4,%5,%6,%7}, {%8,%9}, {%0,%1,%2,%3};"
        : "+f"(c[0]), "+f"(c[1]), "+f"(c[2]), "+f"(c[3])
        : "r"(a[0]), "r"(a[1]), "r"(a[2]), "r"(a[3]), "r"(b0), "r"(b1));
}

// ======================= scratch device globals ==============================
__device__ __align__(16) __nv_bfloat16 g_pbf[M_COLS * D_DIM];
__device__ float  g_sum_x[D_DIM];
__device__ float  g_sum_nx2;
__device__ float  g_nx2[N_ROWS];
__device__ float4 g_pstat[M_COLS];   // {np2, 1/(||p||*sqrt(ssd)), psi, cos(G+psi)}
__device__ double g_acc;

// ======================= prep kernels ========================================
__global__ void init_kernel() {
    int t = threadIdx.x;
    if (t < D_DIM) g_sum_x[t] = 0.f;
    if (t == 0) { g_sum_nx2 = 0.f; g_acc = 0.0; }
}

// per-row ||x||^2 + column sums (block-level smem reduce, few atomics)
__global__ void xstats_kernel(const float* __restrict__ x) {
    __shared__ float ssx[8][128];
    __shared__ float ssn[8];
    int lane = threadIdx.x & 31;
    int wid  = threadIdx.x >> 5;
    int base = (blockIdx.x * 8 + wid) * 8;

    float sx0 = 0.f, sx1 = 0.f, sx2 = 0.f, sx3 = 0.f;
    float snx2 = 0.f;
    #pragma unroll
    for (int rr = 0; rr < 8; ++rr) {
        int row = base + rr;
        float4 v = ((const float4*)(x + (size_t)row * D_DIM))[lane];
        float d = v.x*v.x + v.y*v.y + v.z*v.z + v.w*v.w;
        snx2 += d;
        float dr = d;
        #pragma unroll
        for (int o = 16; o; o >>= 1) dr += __shfl_xor_sync(0xffffffffu, dr, o);
        if (lane == 0) g_nx2[row] = dr;
        sx0 += v.x; sx1 += v.y; sx2 += v.z; sx3 += v.w;
    }
    ssx[wid][lane*4+0] = sx0; ssx[wid][lane*4+1] = sx1;
    ssx[wid][lane*4+2] = sx2; ssx[wid][lane*4+3] = sx3;
    #pragma unroll
    for (int o = 16; o; o >>= 1) snx2 += __shfl_xor_sync(0xffffffffu, snx2, o);
    if (lane == 0) ssn[wid] = snx2;
    __syncthreads();
    if (threadIdx.x < 128) {
        float s = 0.f;
        #pragma unroll
        for (int w = 0; w < 8; ++w) s += ssx[w][threadIdx.x];
        atomicAdd(&g_sum_x[threadIdx.x], s);
    }
    if (threadIdx.x == 0) {
        float s = 0.f;
        #pragma unroll
        for (int w = 0; w < 8; ++w) s += ssn[w];
        atomicAdd(&g_sum_nx2, s);
    }
}

// warp-per-column: lane owns 4 dims, coalesced bf16 writes
__global__ void pstats_kernel(const float* __restrict__ p) {
    int j    = blockIdx.x * 8 + (threadIdx.x >> 5);
    int lane = threadIdx.x & 31;
    if (j >= M_COLS) return;
    float4 v = ((const float4*)(p + (size_t)j * D_DIM))[lane];
    float4 s = ((const float4*)g_sum_x)[lane];
    float np2   = v.x*v.x + v.y*v.y + v.z*v.z + v.w*v.w;
    float sxdot = v.x*s.x + v.y*s.y + v.z*s.z + v.w*s.w;
    __nv_bfloat162 h0 = __floats2bfloat162_rn(v.x, v.y);
    __nv_bfloat162 h1 = __floats2bfloat162_rn(v.z, v.w);
    uint2 hi = make_uint2(*(uint32_t*)&h0, *(uint32_t*)&h1);
    *(uint2*)(g_pbf + (size_t)j * D_DIM + lane * 4) = hi;
    #pragma unroll
    for (int o = 16; o; o >>= 1) {
        np2   += __shfl_xor_sync(0xffffffffu, np2, o);
        sxdot += __shfl_xor_sync(0xffffffffu, sxdot, o);
    }
    if (lane == 0) {
        float ssd    = g_sum_nx2 + (float)N_ROWS * np2 - 2.f * sxdot;
        float inv_np = rsqrtf(np2);
        float invc   = rsqrtf(np2 * ssd);
        float psi    = asinf(K_CONST * (1.f - np2) * inv_np);
        float c1     = cosf(GAMMA_CONST + psi);   // zero-contribution threshold
        g_pstat[j]   = make_float4(np2, invc, psi, c1);
    }
}

// ======================= main fused kernel ===================================
// SMEM map (bytes):
#define SM_RED 0                       // 16 floats + pad
#define SM_PS  128                     // full pstat: 2048 * 16 = 32768
#define SM_A   (SM_PS + 32768)         // 32768
#define SM_B   (SM_A + 32768)          // 2 x 32768
#define SMEM_TOTAL (SM_B + 2 * 32768)  // 131200
#define NTHREADS 512

// Tile stored as [128 rows][16 chunks of 16B]; phys chunk = c ^ (row & 7).
__device__ __forceinline__ uint32_t sw_off(int row, int c) {
    return (uint32_t)(row * 256 + ((c ^ (row & 7)) << 4));
}

__device__ __forceinline__ void load_b_tile(uint32_t sb, int buf, int t) {
    const int tid = threadIdx.x;
    const uint32_t bh = sb + SM_B + buf * 32768u;
    const size_t rbase = (size_t)t * 128 * D_DIM;
    #pragma unroll
    for (int i = 0; i < 4; ++i) {
        int idx = tid + i * NTHREADS;
        int row = idx >> 4, c = idx & 15;
        uint32_t off = sw_off(row, c);
        size_t src = rbase + (size_t)row * D_DIM + c * 8;
        CPA16(bh + off, (const void*)(g_pbf + src));
    }
}

// fast acos via A&S 4.4.45 (|err| <= 2e-8), sqrt.approx
__device__ __forceinline__ float acos_fast(float x) {
    float ax = fabsf(x);
    float s;
    asm("sqrt.approx.f32 %0, %1;" : "=f"(s) : "f"(1.0f - ax));
    float p = -0.0012624911f;
    p = fmaf(p, ax,  0.0066700901f);
    p = fmaf(p, ax, -0.0170881256f);
    p = fmaf(p, ax,  0.0308918810f);
    p = fmaf(p, ax, -0.0501743046f);
    p = fmaf(p, ax,  0.0889789874f);
    p = fmaf(p, ax, -0.2145988016f);
    p = fmaf(p, ax,  1.5707963050f);
    float r = s * p;
    return (x < 0.f) ? (3.14159265358979f - r) : r;
}

__global__ void __launch_bounds__(NTHREADS, 1)
main_kernel(const float* __restrict__ x, const int* __restrict__ labels) {
    extern __shared__ char smem[];
    const uint32_t sb = smem_u32(smem);
    const int tid = threadIdx.x;
    const int wid = tid >> 5, lane = tid & 31;
    const int rowBase = blockIdx.x * 128;
    const int warpRow = (wid & 3) * 32;      // 32-row slab
    const int warpCol = (wid >> 2) * 32;     // 32-col slab (16 warps: 4x4)
    const int gid = lane >> 2, tig = lane & 3;
    const int lrow = lane & 15, side = lane >> 4, l7 = lane & 7;

    // ---- async loads: full pstat (32KB), B tiles 0 and 1 ----
    #pragma unroll
    for (int i = 0; i < 4; ++i) {
        int idx = tid + i * NTHREADS;
        CPA16(sb + SM_PS + idx * 16, (const void*)(g_pstat + idx));
    }
    load_b_tile(sb, 0, 0);
    load_b_tile(sb, 1, 1);
    CPA_COMMIT();

    // ---- A: load fp32 x tile, round to bf16 in smem ----
    #pragma unroll
    for (int i = 0; i < 4; ++i) {
        int idx = tid + i * NTHREADS;          // 2048 16B-chunks
        int row = idx >> 4, c = idx & 15;
        const float4* src = (const float4*)(x + (size_t)(rowBase + row) * D_DIM + c * 8);
        float4 a = src[0], b = src[1];
        __nv_bfloat162 h0 = __floats2bfloat162_rn(a.x, a.y);
        __nv_bfloat162 h1 = __floats2bfloat162_rn(a.z, a.w);
        __nv_bfloat162 h2 = __floats2bfloat162_rn(b.x, b.y);
        __nv_bfloat162 h3 = __floats2bfloat162_rn(b.z, b.w);
        uint4 h = make_uint4(*(uint32_t*)&h0, *(uint32_t*)&h1,
                             *(uint32_t*)&h2, *(uint32_t*)&h3);
        *(uint4*)(smem + SM_A + sw_off(row, c)) = h;
    }

    // ---- per-thread row constants ----
    float bx4[4]; int lab4[4];
    #pragma unroll
    for (int mt = 0; mt < 2; ++mt)
        #pragma unroll
        for (int h = 0; h < 2; ++h) {
            int r = rowBase + warpRow + mt * 16 + gid + h * 8;
            bx4[mt * 2 + h]  = g_nx2[r];
            lab4[mt * 2 + h] = labels[r];
        }

    CPA_WAIT0();
    __syncthreads();

    const uint32_t AH = sb + SM_A;
    const float4* pss = (const float4*)(smem + SM_PS);

    float acc[2][2][4][4];   // [bank][mt][nt][q]
    float local = 0.f;

    // ---- MMA for one tile from buffer `buf` into bank `pb` (single pass) ----
    auto mma_tile = [&](int buf, int pb) {
        const uint32_t BH = sb + SM_B + buf * 32768u;
        #pragma unroll
        for (int mt = 0; mt < 2; ++mt)
            #pragma unroll
            for (int nt = 0; nt < 4; ++nt)
                #pragma unroll
                for (int q = 0; q < 4; ++q) acc[pb][mt][nt][q] = 0.f;
        #pragma unroll
        for (int ks = 0; ks < 8; ++ks) {
            const uint32_t kc = (uint32_t)(((ks * 2 + side) ^ l7) << 4);
            uint32_t a0[4], a1[4];
            ldsm4(a0, AH + (uint32_t)(warpRow      + lrow) * 256 + kc);
            ldsm4(a1, AH + (uint32_t)(warpRow + 16 + lrow) * 256 + kc);
            #pragma unroll
            for (int tp = 0; tp < 2; ++tp) {
                uint32_t b[4];
                ldsm4(b, BH + (uint32_t)(warpCol + tp * 16 + lrow) * 256 + kc);
                mma16816(acc[pb][0][tp*2],   a0, b[0], b[2]);
                mma16816(acc[pb][0][tp*2+1], a0, b[1], b[3]);
                mma16816(acc[pb][1][tp*2],   a1, b[0], b[2]);
                mma16816(acc[pb][1][tp*2+1], a1, b[1], b[3]);
            }
        }
    };

    // ---- epilogue for tile t from bank pb ----
    auto epilogue = [&](int t, int pb) {
        const int colBase = t * 128 + warpCol;
        #pragma unroll
        for (int nt = 0; nt < 4; ++nt) {
            const int ci = colBase + nt * 8 + tig * 2;
            const float4 psA = pss[ci];
            const float4 ps1 = pss[ci + 1];
            #pragma unroll
            for (int mt = 0; mt < 2; ++mt)
                #pragma unroll
                for (int h = 0; h < 2; ++h) {
                    const int   ri  = mt * 2 + h;
                    const float bxv = bx4[ri];
                    const float b1v = 1.f + bxv;
                    const int   rl  = lab4[ri];
                    #pragma unroll
                    for (int e = 0; e < 2; ++e) {
                        const float4 ps = e ? ps1 : psA;
                        float dot   = acc[pb][mt][nt][h * 2 + e];
                        float num   = fmaf(ps.x, dot - b1v, dot);       // dot(1+np2)-np2(1+nx2)
                        float tt    = fmaf(-2.f, dot, fmaf(ps.x, bxv, 1.f));
                        float ratio = num * ps.y * rsqrtf(tt);
                        bool  isl   = (ci + e == rl);
                        if (ratio > ps.w || isl) {                      // else contribution = 0
                            float rc    = fminf(1.f, fmaxf(-1.f, ratio));
                            float angle = acos_fast(rc);
                            float ang   = fmaxf(0.f, angle - ps.z);
                            float hinge = fmaxf(0.f, GAMMA_CONST - ang);
                            local += isl ? ang : hinge;
                        }
                    }
                }
        }
    };

    // ---- pipelined loop: MMA(t+1) issued before epilogue(t) ----
    mma_tile(0, 0);
    for (int tb = 0; tb < 16; tb += 2) {
        #pragma unroll
        for (int u = 0; u < 2; ++u) {
            const int t = tb + u;
            if (t < 15) {
                CPA_WAIT0();
                __syncthreads();
                if (t < 14) { load_b_tile(sb, t & 1, t + 2); CPA_COMMIT(); }
                mma_tile((t + 1) & 1, (u + 1) & 1);
            }
            epilogue(t, u);
        }
    }

    // ---- block reduction -> one double atomic per CTA ----
    #pragma unroll
    for (int o = 16; o; o >>= 1) local += __shfl_xor_sync(0xffffffffu, local, o);
    float* red = (float*)(smem + SM_RED);
    if (lane == 0) red[wid] = local;
    __syncthreads();
    if (tid == 0) {
        float s = 0.f;
        #pragma unroll
        for (int w = 0; w < 16; ++w) s += red[w];
        atomicAdd(&g_acc, (double)s);
    }
}

__global__ void finish_kernel(float* __restrict__ out) {
    out[0] = (float)(g_acc / (double)N_ROWS);
}

// ======================= launch ==============================================
extern "C" void kernel_launch(void* const* d_in, const int* in_sizes, int n_in,
                              void* d_out, int out_size) {
    const float* x      = (const float*)d_in[0];
    const float* p      = (const float*)d_in[1];
    const int*   labels = (const int*)d_in[2];
    float* out = (float*)d_out;

    cudaFuncSetAttribute(main_kernel, cudaFuncAttributeMaxDynamicSharedMemorySize, SMEM_TOTAL);

    init_kernel<<<1, 128>>>();
    xstats_kernel<<<256, 256>>>(x);
    pstats_kernel<<<256, 256>>>(p);
    main_kernel<<<128, NTHREADS, SMEM_TOTAL>>>(x, labels);
    finish_kernel<<<1, 1>>>(out);
}